// round 12
// baseline (speedup 1.0000x reference)
#include <cuda_runtime.h>
#include <cstdint>

#define N_FFT 8192
#define NT    512
#define D_CH  512
#define SEQ   4096
#define NBATCH 4

// Padded smem index: +1 float2 every 16
#define PADI(i) ((i) + ((i) >> 4))
#define BUFSZ (N_FFT + (N_FFT >> 4))   // 8704 float2 = 69632 B

__device__ float2 g_tw[N_FFT];                          // exp(-2*pi*i*k/N)
__device__ float2 g_tfft[(size_t)D_CH * N_FFT];         // t spectra (33.5 MB)
__device__ float  g_xT[(size_t)NBATCH * D_CH * SEQ];
__device__ float  g_tT[(size_t)D_CH * 2 * SEQ];
__device__ float  g_oT[(size_t)NBATCH * D_CH * SEQ];

__device__ __forceinline__ float2 cadd(float2 a, float2 b) { return make_float2(a.x + b.x, a.y + b.y); }
__device__ __forceinline__ float2 csub(float2 a, float2 b) { return make_float2(a.x - b.x, a.y - b.y); }
__device__ __forceinline__ float2 cmul(float2 a, float2 b) {
    return make_float2(a.x * b.x - a.y * b.y, a.x * b.y + a.y * b.x);
}
template <bool INV>
__device__ __forceinline__ float2 mulJ(float2 z) {
    return INV ? make_float2(-z.y, z.x) : make_float2(z.y, -z.x);
}
template <bool INV>
__device__ __forceinline__ float2 twc(float2 z, float re, float im) {
    float2 w = make_float2(re, INV ? -im : im);
    return cmul(z, w);
}

template <bool INV>
__device__ __forceinline__ void dft4(float2& a0, float2& a1, float2& a2, float2& a3) {
    float2 t0 = cadd(a0, a2), t1 = csub(a0, a2);
    float2 t2 = cadd(a1, a3), t3 = mulJ<INV>(csub(a1, a3));
    a0 = cadd(t0, t2);
    a1 = cadd(t1, t3);
    a2 = csub(t0, t2);
    a3 = csub(t1, t3);
}

template <bool INV>
__device__ __forceinline__ void dft16(float2 a[16]) {
    const float C1 = 0.92387953251128675613f;
    const float S1 = 0.38268343236508977173f;
    const float H  = 0.70710678118654752440f;
#pragma unroll
    for (int ji = 0; ji < 4; ji++) dft4<INV>(a[ji], a[ji + 4], a[ji + 8], a[ji + 12]);
    a[5]  = twc<INV>(a[5],  C1, -S1);
    a[9]  = twc<INV>(a[9],   H,  -H);
    a[13] = twc<INV>(a[13], S1, -C1);
    a[6]  = twc<INV>(a[6],   H,  -H);
    a[10] = mulJ<INV>(a[10]);
    a[14] = twc<INV>(a[14], -H,  -H);
    a[7]  = twc<INV>(a[7],  S1, -C1);
    a[11] = twc<INV>(a[11], -H,  -H);
    a[15] = twc<INV>(a[15], -C1, S1);
#pragma unroll
    for (int ro = 0; ro < 4; ro++) dft4<INV>(a[4 * ro], a[4 * ro + 1], a[4 * ro + 2], a[4 * ro + 3]);
}

template <bool INV>
__device__ __forceinline__ void tw_load(int sLog, int tid, float2& w1, float2& w8) {
    const int tb = (tid >> sLog) << sLog;
    w1 = g_tw[tb];
    w8 = g_tw[tb << 3];
    if (INV) { w1.y = -w1.y; w8.y = -w8.y; }
}

__device__ __forceinline__ void pass16_write(float2* __restrict__ X, const float2 a[16],
                                             int sLog, int tid, float2 w1, float2 w8) {
    constexpr int SW16[16] = {0,4,8,12, 1,5,9,13, 2,6,10,14, 3,7,11,15};
    const int q = tid & ((1 << sLog) - 1);
    const int p = tid >> sLog;
    const int ob = q + (p << (sLog + 4));
    X[PADI(ob)] = a[SW16[0]];
    float2 w = w1;
#pragma unroll
    for (int r = 1; r < 8; r++) {
        X[PADI(ob + (r << sLog))] = cmul(a[SW16[r]], w);
        w = cmul(w, w1);
    }
    X[PADI(ob + (8 << sLog))] = cmul(a[SW16[8]], w8);
    w = cmul(w8, w1);
#pragma unroll
    for (int r = 9; r < 16; r++) {
        X[PADI(ob + (r << sLog))] = cmul(a[SW16[r]], w);
        w = cmul(w, w1);
    }
}

template <bool INV>
__device__ __forceinline__ void pass16(float2* __restrict__ X, int sLog, int tid) {
    float2 a[16];
#pragma unroll
    for (int r = 0; r < 16; r++) a[r] = X[PADI(tid + 512 * r)];
    dft16<INV>(a);
    float2 w1, w8;
    tw_load<INV>(sLog, tid, w1, w8);   // overlaps the barrier wait
    __syncthreads();
    pass16_write(X, a, sLog, tid, w1, w8);
    __syncthreads();
}

// Generic 64x64 float4 transpose tile body for 512-thread fat kernels.
// in[b-slice]: R x C (row-major), out: C x R. tile = smem scratch (>= 64*65 floats).
__device__ __forceinline__ void t4_tile512(const float* __restrict__ I, float* __restrict__ O,
                                           int R, int C, int r0, int c0, float* tile, int tid) {
#pragma unroll
    for (int k = 0; k < 2; k++) {
        int idx = k * 512 + tid;                  // 0..1023
        int row = idx >> 4, c4 = idx & 15;
        float4 v = *reinterpret_cast<const float4*>(I + (size_t)(r0 + row) * C + c0 + 4 * c4);
        tile[row * 65 + 4 * c4 + 0] = v.x;
        tile[row * 65 + 4 * c4 + 1] = v.y;
        tile[row * 65 + 4 * c4 + 2] = v.z;
        tile[row * 65 + 4 * c4 + 3] = v.w;
    }
    __syncthreads();
#pragma unroll
    for (int k = 0; k < 2; k++) {
        int idx = k * 512 + tid;
        int c = idx >> 4, r4 = idx & 15;
        float4 v = make_float4(tile[(4 * r4 + 0) * 65 + c], tile[(4 * r4 + 1) * 65 + c],
                               tile[(4 * r4 + 2) * 65 + c], tile[(4 * r4 + 3) * 65 + c]);
        *reinterpret_cast<float4*>(O + (size_t)(c0 + c) * R + r0 + 4 * r4) = v;
    }
}

// Conv body for one (pr, d) unit. X = smem buffer.
__device__ __forceinline__ void conv_body(float2* __restrict__ X, int pr, int d, int tid) {
    const float* x0 = g_xT + ((size_t)(2 * pr) * D_CH + d) * SEQ;
    const float* x1 = x0 + (size_t)D_CH * SEQ;

    // forward pass 0 fused with gmem load (zero-pad r>=8)
    {
        float2 a[16];
#pragma unroll
        for (int r = 0; r < 8; r++)
            a[r] = make_float2(x0[tid + 512 * r], x1[tid + 512 * r]);
#pragma unroll
        for (int r = 8; r < 16; r++) a[r] = make_float2(0.0f, 0.0f);
        dft16<false>(a);
        float2 w1, w8;
        tw_load<false>(0, tid, w1, w8);
        pass16_write(X, a, 0, tid, w1, w8);
        __syncthreads();
    }
    pass16<false>(X, 4, tid);
    pass16<false>(X, 8, tid);

    // Fused: forward final radix-2 + pointwise multiply (+1/N) + inverse pass 0.
    {
        const float2* tf = g_tfft + (size_t)d * N_FFT;
        const float inv = 1.0f / (float)N_FFT;
        float2 a[16];
#pragma unroll
        for (int i = 0; i < 8; i++) {
            int q = tid + 512 * i;
            float2 u = X[PADI(q)];
            float2 v = X[PADI(q + 4096)];
            float2 s = cmul(cadd(u, v), tf[q]);
            float2 dd = cmul(csub(u, v), tf[q + 4096]);
            a[i]     = make_float2(s.x * inv, s.y * inv);
            a[i + 8] = make_float2(dd.x * inv, dd.y * inv);
        }
        dft16<true>(a);
        float2 w1, w8;
        tw_load<true>(0, tid, w1, w8);
        __syncthreads();
        pass16_write(X, a, 0, tid, w1, w8);
        __syncthreads();
    }
    pass16<true>(X, 4, tid);
    pass16<true>(X, 8, tid);

    // final radix-2 of inverse: only first half needed -> sum only, straight to gmem
    float* o0 = g_oT + ((size_t)(2 * pr) * D_CH + d) * SEQ;
    float* o1 = o0 + (size_t)D_CH * SEQ;
#pragma unroll
    for (int i = 0; i < 8; i++) {
        int q = tid + 512 * i;
        float2 s = cadd(X[PADI(q)], X[PADI(q + 4096)]);
        o0[q] = s.x;
        o1[q] = s.y;
    }
}

// ---------------------------------------------------------------------------
// float4 tiled transpose (256 threads): in[b][r][c] -> out[b][c][r]. 64x64 tiles.
// If fill_tw != 0, the first 32 blocks also populate g_tw.
__global__ void __launch_bounds__(256) ker_T4(const float* __restrict__ in, float* __restrict__ out,
                                              int R, int C, int fill_tw) {
    __shared__ float tile[64][65];
    if (fill_tw && blockIdx.z == 0) {
        int fb = blockIdx.x + blockIdx.y * gridDim.x;
        if (fb < 32) {
            int k = fb * 256 + threadIdx.x;
            float s, c;
            sincospif(-2.0f * (float)k / (float)N_FFT, &s, &c);
            g_tw[k] = make_float2(c, s);
        }
    }
    const size_t boff = (size_t)blockIdx.z * R * C;
    const float* I = in + boff;
    float* O = out + boff;
    const int c0 = blockIdx.x * 64, r0 = blockIdx.y * 64;
    const int tid = threadIdx.x;
#pragma unroll
    for (int k = 0; k < 4; k++) {
        int idx = k * 256 + tid;
        int row = idx >> 4;
        int c4  = idx & 15;
        float4 v = *reinterpret_cast<const float4*>(I + (size_t)(r0 + row) * C + c0 + 4 * c4);
        tile[row][4 * c4 + 0] = v.x;
        tile[row][4 * c4 + 1] = v.y;
        tile[row][4 * c4 + 2] = v.z;
        tile[row][4 * c4 + 3] = v.w;
    }
    __syncthreads();
#pragma unroll
    for (int k = 0; k < 4; k++) {
        int idx = k * 256 + tid;
        int c  = idx >> 4;
        int r4 = idx & 15;
        float4 v = make_float4(tile[4 * r4 + 0][c], tile[4 * r4 + 1][c],
                               tile[4 * r4 + 2][c], tile[4 * r4 + 3][c]);
        *reinterpret_cast<float4*>(O + (size_t)(c0 + c) * R + r0 + 4 * r4) = v;
    }
}

// Fat kernel: blocks [0,256) tfft; blocks [256,1280) transpose x batches 0,1.
__global__ void __launch_bounds__(NT, 2) ker_xT_tfft(const float* __restrict__ x) {
    extern __shared__ float2 sm[];
    const int tid = threadIdx.x;

    if (blockIdx.x >= 256) {
        const int tt = blockIdx.x - 256;              // 0..1023
        const int b = tt >> 9;                        // 0,1
        const int rem = tt & 511;
        const int c0 = (rem & 7) * 64;                // C=512 channels
        const int r0 = (rem >> 3) * 64;               // R=4096 seq
        t4_tile512(x + (size_t)b * SEQ * D_CH, g_xT + (size_t)b * SEQ * D_CH,
                   SEQ, D_CH, r0, c0, reinterpret_cast<float*>(sm), tid);
        return;
    }

    // tfft: block handles channels (2c0, 2c0+1) as real+imag of one FFT
    float2* X = sm;
    const int c0 = blockIdx.x;
    const float* t0 = g_tT + (size_t)(2 * c0) * N_FFT;
    const float* t1 = t0 + N_FFT;
    {
        float2 a[16];
#pragma unroll
        for (int r = 0; r < 16; r++)
            a[r] = make_float2(t0[tid + 512 * r], t1[tid + 512 * r]);
        dft16<false>(a);
        float2 w1, w8;
        tw_load<false>(0, tid, w1, w8);
        pass16_write(X, a, 0, tid, w1, w8);
        __syncthreads();
    }
    pass16<false>(X, 4, tid);
    pass16<false>(X, 8, tid);

    float2* out0 = g_tfft + (size_t)(2 * c0) * N_FFT;
    float2* out1 = g_tfft + (size_t)(2 * c0 + 1) * N_FFT;
#pragma unroll
    for (int i = 0; i < 16; i++) {
        int k = tid + 512 * i;
        int kl = k & 4095;
        float2 ua = X[PADI(kl)], ub = X[PADI(kl + 4096)];
        float2 Zk = (k < 4096) ? cadd(ua, ub) : csub(ua, ub);
        int kn = (N_FFT - k) & (N_FFT - 1);
        int knl = kn & 4095;
        float2 va = X[PADI(knl)], vb = X[PADI(knl + 4096)];
        float2 Zn = (kn < 4096) ? cadd(va, vb) : csub(va, vb);
        out0[k] = make_float2(0.5f * (Zk.x + Zn.x), 0.5f * (Zk.y - Zn.y));
        out1[k] = make_float2(0.5f * (Zk.y + Zn.y), -0.5f * (Zk.x - Zn.x));
    }
}

// Fat A: blocks [0,512) conv(pr=0); blocks [512,1536) transpose x batches 2,3.
__global__ void __launch_bounds__(NT, 2) ker_convA(const float* __restrict__ x) {
    extern __shared__ float2 sm[];
    const int tid = threadIdx.x;
    if (blockIdx.x < 512) {
        conv_body(sm, 0, blockIdx.x, tid);
        return;
    }
    const int tt = blockIdx.x - 512;                  // 0..1023
    const int b = 2 + (tt >> 9);                      // 2,3
    const int rem = tt & 511;
    const int c0 = (rem & 7) * 64;
    const int r0 = (rem >> 3) * 64;
    t4_tile512(x + (size_t)b * SEQ * D_CH, g_xT + (size_t)b * SEQ * D_CH,
               SEQ, D_CH, r0, c0, reinterpret_cast<float*>(sm), tid);
}

// Fat B: blocks [0,512) conv(pr=1); blocks [512,1536) o-transpose batches 0,1.
__global__ void __launch_bounds__(NT, 2) ker_convB(float* __restrict__ o) {
    extern __shared__ float2 sm[];
    const int tid = threadIdx.x;
    if (blockIdx.x < 512) {
        conv_body(sm, 1, blockIdx.x, tid);
        return;
    }
    const int tt = blockIdx.x - 512;                  // 0..1023
    const int b = tt >> 9;                            // 0,1
    const int rem = tt & 511;
    // oT (b, 512ch, 4096seq) -> o (b, 4096, 512): R=512, C=4096
    const int c0 = (rem & 63) * 64;                   // C=4096 seq
    const int r0 = (rem >> 6) * 64;                   // R=512 channels
    t4_tile512(g_oT + (size_t)b * SEQ * D_CH, o + (size_t)b * SEQ * D_CH,
               D_CH, SEQ, r0, c0, reinterpret_cast<float*>(sm), tid);
}

extern "C" void kernel_launch(void* const* d_in, const int* in_sizes, int n_in,
                              void* d_out, int out_size) {
    const float* x = (const float*)d_in[0];
    const float* t = (const float*)d_in[1];
    if (n_in >= 2 && in_sizes[0] < in_sizes[1]) {
        const float* tmp = x; x = t; t = tmp;
    }
    float* o = (float*)d_out;

    float* tT;  cudaGetSymbolAddress((void**)&tT, g_tT);
    float* oT;  cudaGetSymbolAddress((void**)&oT, g_oT);

    const size_t smem = (size_t)BUFSZ * sizeof(float2);  // 69632 B -> 2 blocks/SM
    cudaFuncSetAttribute(ker_xT_tfft, cudaFuncAttributeMaxDynamicSharedMemorySize, (int)smem);
    cudaFuncSetAttribute(ker_convA, cudaFuncAttributeMaxDynamicSharedMemorySize, (int)smem);
    cudaFuncSetAttribute(ker_convB, cudaFuncAttributeMaxDynamicSharedMemorySize, (int)smem);

    {
        dim3 blk(256);
        dim3 gt(D_CH / 64, (2 * SEQ) / 64, 1);
        ker_T4<<<gt, blk>>>(t, tT, 2 * SEQ, D_CH, 1);   // also fills g_tw
    }

    ker_xT_tfft<<<256 + 1024, NT, smem>>>(x);           // tfft + xT batches 0,1
    ker_convA<<<512 + 1024, NT, smem>>>(x);             // conv pr=0 + xT batches 2,3
    ker_convB<<<512 + 1024, NT, smem>>>(o);             // conv pr=1 + oT->o batches 0,1

    {
        dim3 blk(256);
        dim3 go(SEQ / 64, D_CH / 64, 2);                // o-transpose batches 2,3
        ker_T4<<<go, blk>>>(oT + (size_t)2 * SEQ * D_CH, o + (size_t)2 * SEQ * D_CH,
                            D_CH, SEQ, 0);
    }
}

// round 13
// speedup vs baseline: 1.0128x; 1.0128x over previous
#include <cuda_runtime.h>
#include <cstdint>

#define N_FFT 8192
#define NT    512
#define D_CH  512
#define SEQ   4096
#define NBATCH 4

// Padded smem index: +1 float2 every 16
#define PADI(i) ((i) + ((i) >> 4))
#define BUFSZ (N_FFT + (N_FFT >> 4))   // 8704 float2 = 69632 B

__device__ float2 g_tw[N_FFT];                       // exp(-2*pi*i*k/N)
__device__ float4 g_tfft[(size_t)D_CH * SEQ];        // [d][q] = (T[q], T[q+4096])  33.5 MB
__device__ float2 g_xP[(size_t)2 * D_CH * SEQ];      // [pair][d][n] = (x_b0, x_b1) 33.5 MB
__device__ float  g_tT[(size_t)D_CH * 2 * SEQ];
__device__ float2 g_oP[(size_t)2 * D_CH * SEQ];      // [pair][d][n] = (o_b0, o_b1)

__device__ __forceinline__ float2 cadd(float2 a, float2 b) { return make_float2(a.x + b.x, a.y + b.y); }
__device__ __forceinline__ float2 csub(float2 a, float2 b) { return make_float2(a.x - b.x, a.y - b.y); }
__device__ __forceinline__ float2 cmul(float2 a, float2 b) {
    return make_float2(a.x * b.x - a.y * b.y, a.x * b.y + a.y * b.x);
}
template <bool INV>
__device__ __forceinline__ float2 mulJ(float2 z) {
    return INV ? make_float2(-z.y, z.x) : make_float2(z.y, -z.x);
}
template <bool INV>
__device__ __forceinline__ float2 twc(float2 z, float re, float im) {
    float2 w = make_float2(re, INV ? -im : im);
    return cmul(z, w);
}

template <bool INV>
__device__ __forceinline__ void dft4(float2& a0, float2& a1, float2& a2, float2& a3) {
    float2 t0 = cadd(a0, a2), t1 = csub(a0, a2);
    float2 t2 = cadd(a1, a3), t3 = mulJ<INV>(csub(a1, a3));
    a0 = cadd(t0, t2);
    a1 = cadd(t1, t3);
    a2 = csub(t0, t2);
    a3 = csub(t1, t3);
}

template <bool INV>
__device__ __forceinline__ void dft16(float2 a[16]) {
    const float C1 = 0.92387953251128675613f;
    const float S1 = 0.38268343236508977173f;
    const float H  = 0.70710678118654752440f;
#pragma unroll
    for (int ji = 0; ji < 4; ji++) dft4<INV>(a[ji], a[ji + 4], a[ji + 8], a[ji + 12]);
    a[5]  = twc<INV>(a[5],  C1, -S1);
    a[9]  = twc<INV>(a[9],   H,  -H);
    a[13] = twc<INV>(a[13], S1, -C1);
    a[6]  = twc<INV>(a[6],   H,  -H);
    a[10] = mulJ<INV>(a[10]);
    a[14] = twc<INV>(a[14], -H,  -H);
    a[7]  = twc<INV>(a[7],  S1, -C1);
    a[11] = twc<INV>(a[11], -H,  -H);
    a[15] = twc<INV>(a[15], -C1, S1);
#pragma unroll
    for (int ro = 0; ro < 4; ro++) dft4<INV>(a[4 * ro], a[4 * ro + 1], a[4 * ro + 2], a[4 * ro + 3]);
}

template <bool INV>
__device__ __forceinline__ void tw_load(int sLog, int tid, float2& w1, float2& w8) {
    const int tb = (tid >> sLog) << sLog;
    w1 = g_tw[tb];
    w8 = g_tw[tb << 3];
    if (INV) { w1.y = -w1.y; w8.y = -w8.y; }
}

__device__ __forceinline__ void pass16_write(float2* __restrict__ X, const float2 a[16],
                                             int sLog, int tid, float2 w1, float2 w8) {
    constexpr int SW16[16] = {0,4,8,12, 1,5,9,13, 2,6,10,14, 3,7,11,15};
    const int q = tid & ((1 << sLog) - 1);
    const int p = tid >> sLog;
    const int ob = q + (p << (sLog + 4));
    X[PADI(ob)] = a[SW16[0]];
    float2 w = w1;
#pragma unroll
    for (int r = 1; r < 8; r++) {
        X[PADI(ob + (r << sLog))] = cmul(a[SW16[r]], w);
        w = cmul(w, w1);
    }
    X[PADI(ob + (8 << sLog))] = cmul(a[SW16[8]], w8);
    w = cmul(w8, w1);
#pragma unroll
    for (int r = 9; r < 16; r++) {
        X[PADI(ob + (r << sLog))] = cmul(a[SW16[r]], w);
        w = cmul(w, w1);
    }
}

template <bool INV>
__device__ __forceinline__ void pass16(float2* __restrict__ X, int sLog, int tid) {
    float2 a[16];
#pragma unroll
    for (int r = 0; r < 16; r++) a[r] = X[PADI(tid + 512 * r)];
    dft16<INV>(a);
    float2 w1, w8;
    tw_load<INV>(sLog, tid, w1, w8);   // overlaps the barrier wait
    __syncthreads();
    pass16_write(X, a, sLog, tid, w1, w8);
    __syncthreads();
}

// ---------------------------------------------------------------------------
// x pair-transpose tile (512 threads): reads batches b0,b1 tile [n0..+64)x[d0..+64),
// writes g_xP-style interleaved (d, n) float2 layout. t0,t1: 64*65 floats each.
__device__ __forceinline__ void xP_tile(const float* __restrict__ xb0, const float* __restrict__ xb1,
                                        float2* __restrict__ outP, int n0, int d0,
                                        float* t0, float* t1, int tid) {
#pragma unroll
    for (int k = 0; k < 2; k++) {
        int idx = k * 512 + tid;                 // 0..1023
        int n = idx >> 4, c4 = idx & 15;
        float4 v0 = *reinterpret_cast<const float4*>(xb0 + (size_t)(n0 + n) * D_CH + d0 + 4 * c4);
        float4 v1 = *reinterpret_cast<const float4*>(xb1 + (size_t)(n0 + n) * D_CH + d0 + 4 * c4);
        t0[n * 65 + 4 * c4 + 0] = v0.x; t0[n * 65 + 4 * c4 + 1] = v0.y;
        t0[n * 65 + 4 * c4 + 2] = v0.z; t0[n * 65 + 4 * c4 + 3] = v0.w;
        t1[n * 65 + 4 * c4 + 0] = v1.x; t1[n * 65 + 4 * c4 + 1] = v1.y;
        t1[n * 65 + 4 * c4 + 2] = v1.z; t1[n * 65 + 4 * c4 + 3] = v1.w;
    }
    __syncthreads();
#pragma unroll
    for (int k = 0; k < 4; k++) {
        int idx = k * 512 + tid;                 // 0..2047
        int c = idx >> 5, g = idx & 31;
        float4 w = make_float4(t0[(2 * g) * 65 + c], t1[(2 * g) * 65 + c],
                               t0[(2 * g + 1) * 65 + c], t1[(2 * g + 1) * 65 + c]);
        *reinterpret_cast<float4*>(outP + (size_t)(d0 + c) * SEQ + n0 + 2 * g) = w;
    }
}

// o pair-detranspose tile (512 threads): reads g_oP interleaved (d, n), writes o batches.
__device__ __forceinline__ void oP_tile(const float2* __restrict__ inP,
                                        float* __restrict__ ob0, float* __restrict__ ob1,
                                        int n0, int d0, float* t0, float* t1, int tid) {
#pragma unroll
    for (int k = 0; k < 4; k++) {
        int idx = k * 512 + tid;
        int c = idx >> 5, g = idx & 31;
        float4 v = *reinterpret_cast<const float4*>(inP + (size_t)(d0 + c) * SEQ + n0 + 2 * g);
        t0[c * 65 + 2 * g]     = v.x;  t1[c * 65 + 2 * g]     = v.y;
        t0[c * 65 + 2 * g + 1] = v.z;  t1[c * 65 + 2 * g + 1] = v.w;
    }
    __syncthreads();
#pragma unroll
    for (int k = 0; k < 2; k++) {
        int idx = k * 512 + tid;
        int n = idx >> 4, d4 = idx & 15;
        float4 w0 = make_float4(t0[(4 * d4 + 0) * 65 + n], t0[(4 * d4 + 1) * 65 + n],
                                t0[(4 * d4 + 2) * 65 + n], t0[(4 * d4 + 3) * 65 + n]);
        float4 w1 = make_float4(t1[(4 * d4 + 0) * 65 + n], t1[(4 * d4 + 1) * 65 + n],
                                t1[(4 * d4 + 2) * 65 + n], t1[(4 * d4 + 3) * 65 + n]);
        *reinterpret_cast<float4*>(ob0 + (size_t)(n0 + n) * D_CH + d0 + 4 * d4) = w0;
        *reinterpret_cast<float4*>(ob1 + (size_t)(n0 + n) * D_CH + d0 + 4 * d4) = w1;
    }
}

// Conv body for one (pr, d) unit. X = smem buffer.
__device__ __forceinline__ void conv_body(float2* __restrict__ X, int pr, int d, int tid) {
    const float2* xp = g_xP + ((size_t)pr * D_CH + d) * SEQ;

    // forward pass 0 fused with gmem load (zero-pad r>=8); batch pair = one float2 load
    {
        float2 a[16];
#pragma unroll
        for (int r = 0; r < 8; r++) a[r] = xp[tid + 512 * r];
#pragma unroll
        for (int r = 8; r < 16; r++) a[r] = make_float2(0.0f, 0.0f);
        dft16<false>(a);
        float2 w1, w8;
        tw_load<false>(0, tid, w1, w8);
        pass16_write(X, a, 0, tid, w1, w8);
        __syncthreads();
    }
    pass16<false>(X, 4, tid);
    pass16<false>(X, 8, tid);

    // Fused: forward final radix-2 + pointwise multiply (+1/N) + inverse pass 0.
    // tf pair layout: one float4 gives the factors for q and q+4096.
    {
        const float4* tf = g_tfft + (size_t)d * SEQ;
        const float inv = 1.0f / (float)N_FFT;
        float2 a[16];
#pragma unroll
        for (int i = 0; i < 8; i++) {
            int q = tid + 512 * i;
            float4 w = tf[q];
            float2 u = X[PADI(q)];
            float2 v = X[PADI(q + 4096)];
            float2 s = cmul(cadd(u, v), make_float2(w.x, w.y));
            float2 dd = cmul(csub(u, v), make_float2(w.z, w.w));
            a[i]     = make_float2(s.x * inv, s.y * inv);
            a[i + 8] = make_float2(dd.x * inv, dd.y * inv);
        }
        dft16<true>(a);
        float2 w1, w8;
        tw_load<true>(0, tid, w1, w8);
        __syncthreads();
        pass16_write(X, a, 0, tid, w1, w8);
        __syncthreads();
    }
    pass16<true>(X, 4, tid);
    pass16<true>(X, 8, tid);

    // final radix-2 of inverse: sum only, pair-interleaved store (one STG.64 per i)
    float2* op = g_oP + ((size_t)pr * D_CH + d) * SEQ;
#pragma unroll
    for (int i = 0; i < 8; i++) {
        int q = tid + 512 * i;
        op[q] = cadd(X[PADI(q)], X[PADI(q + 4096)]);
    }
}

// ---------------------------------------------------------------------------
// float4 tiled transpose (256 threads) for t; first 32 blocks also fill g_tw.
__global__ void __launch_bounds__(256) ker_T4(const float* __restrict__ in, float* __restrict__ out,
                                              int R, int C, int fill_tw) {
    __shared__ float tile[64][65];
    if (fill_tw && blockIdx.z == 0) {
        int fb = blockIdx.x + blockIdx.y * gridDim.x;
        if (fb < 32) {
            int k = fb * 256 + threadIdx.x;
            float s, c;
            sincospif(-2.0f * (float)k / (float)N_FFT, &s, &c);
            g_tw[k] = make_float2(c, s);
        }
    }
    const size_t boff = (size_t)blockIdx.z * R * C;
    const float* I = in + boff;
    float* O = out + boff;
    const int c0 = blockIdx.x * 64, r0 = blockIdx.y * 64;
    const int tid = threadIdx.x;
#pragma unroll
    for (int k = 0; k < 4; k++) {
        int idx = k * 256 + tid;
        int row = idx >> 4;
        int c4  = idx & 15;
        float4 v = *reinterpret_cast<const float4*>(I + (size_t)(r0 + row) * C + c0 + 4 * c4);
        tile[row][4 * c4 + 0] = v.x;
        tile[row][4 * c4 + 1] = v.y;
        tile[row][4 * c4 + 2] = v.z;
        tile[row][4 * c4 + 3] = v.w;
    }
    __syncthreads();
#pragma unroll
    for (int k = 0; k < 4; k++) {
        int idx = k * 256 + tid;
        int c  = idx >> 4;
        int r4 = idx & 15;
        float4 v = make_float4(tile[4 * r4 + 0][c], tile[4 * r4 + 1][c],
                               tile[4 * r4 + 2][c], tile[4 * r4 + 3][c]);
        *reinterpret_cast<float4*>(O + (size_t)(c0 + c) * R + r0 + 4 * r4) = v;
    }
}

// Fat kernel: blocks [0,256) tfft; blocks [256,1280) x pair-transpose (2 pairs x 512 tiles).
__global__ void __launch_bounds__(NT, 2) ker_xT_tfft(const float* __restrict__ x) {
    extern __shared__ float2 sm[];
    const int tid = threadIdx.x;

    if (blockIdx.x >= 256) {
        const int tt = blockIdx.x - 256;              // 0..1023
        const int p = tt >> 9;                        // pair 0,1
        const int rem = tt & 511;
        const int d0 = (rem & 7) * 64;
        const int n0 = (rem >> 3) * 64;
        const float* xb0 = x + (size_t)(2 * p) * SEQ * D_CH;
        const float* xb1 = xb0 + (size_t)SEQ * D_CH;
        float* t0 = reinterpret_cast<float*>(sm);
        float* t1 = t0 + 64 * 65;
        xP_tile(xb0, xb1, g_xP + (size_t)p * D_CH * SEQ, n0, d0, t0, t1, tid);
        return;
    }

    // tfft: block handles channels (2c0, 2c0+1) as real+imag of one FFT
    float2* X = sm;
    const int c0 = blockIdx.x;
    const float* t0 = g_tT + (size_t)(2 * c0) * N_FFT;
    const float* t1 = t0 + N_FFT;
    {
        float2 a[16];
#pragma unroll
        for (int r = 0; r < 16; r++)
            a[r] = make_float2(t0[tid + 512 * r], t1[tid + 512 * r]);
        dft16<false>(a);
        float2 w1, w8;
        tw_load<false>(0, tid, w1, w8);
        pass16_write(X, a, 0, tid, w1, w8);
        __syncthreads();
    }
    pass16<false>(X, 4, tid);
    pass16<false>(X, 8, tid);

    // Fused: final radix-2 + Hermitian unpack, written in (T[q], T[q+4096]) pair layout.
    // For q < 4096: Z[q] = Y[q]+Y[q+4096], Z[q+4096] = Y[q]-Y[q+4096]; the reversal
    // partner index m = (4096-q)&4095 supplies Z[8192-q] and Z[4096-q].
    float4* out0 = g_tfft + (size_t)(2 * c0) * SEQ;
    float4* out1 = out0 + SEQ;
#pragma unroll
    for (int i = 0; i < 8; i++) {
        int k = tid + 512 * i;
        float2 ua = X[PADI(k)], ub = X[PADI(k + 4096)];
        float2 Zk  = cadd(ua, ub);
        float2 Zk2 = csub(ua, ub);
        int m = (4096 - k) & 4095;
        float2 va = X[PADI(m)], vb = X[PADI(m + 4096)];
        bool kz = (k == 0);
        float2 Zn  = kz ? cadd(va, vb) : csub(va, vb);
        float2 Zn2 = kz ? csub(va, vb) : cadd(va, vb);
        out0[k] = make_float4(0.5f * (Zk.x + Zn.x),  0.5f * (Zk.y - Zn.y),
                              0.5f * (Zk2.x + Zn2.x), 0.5f * (Zk2.y - Zn2.y));
        out1[k] = make_float4(0.5f * (Zk.y + Zn.y),  -0.5f * (Zk.x - Zn.x),
                              0.5f * (Zk2.y + Zn2.y), -0.5f * (Zk2.x - Zn2.x));
    }
}

// Convolution: one block per (batch-pair, channel).
__global__ void __launch_bounds__(NT, 2) ker_conv() {
    extern __shared__ float2 sm[];
    conv_body(sm, blockIdx.x >> 9, blockIdx.x & (D_CH - 1), threadIdx.x);
}

// o pair-detranspose: 1024 tiles (2 pairs x 512), 512 threads, static smem.
__global__ void __launch_bounds__(NT) ker_oP(float* __restrict__ o) {
    __shared__ float t0[64 * 65], t1[64 * 65];
    const int tt = blockIdx.x;
    const int p = tt >> 9;
    const int rem = tt & 511;
    const int d0 = (rem & 7) * 64;
    const int n0 = (rem >> 3) * 64;
    float* ob0 = o + (size_t)(2 * p) * SEQ * D_CH;
    float* ob1 = ob0 + (size_t)SEQ * D_CH;
    oP_tile(g_oP + (size_t)p * D_CH * SEQ, ob0, ob1, n0, d0, t0, t1, threadIdx.x);
}

extern "C" void kernel_launch(void* const* d_in, const int* in_sizes, int n_in,
                              void* d_out, int out_size) {
    const float* x = (const float*)d_in[0];
    const float* t = (const float*)d_in[1];
    if (n_in >= 2 && in_sizes[0] < in_sizes[1]) {
        const float* tmp = x; x = t; t = tmp;
    }
    float* o = (float*)d_out;

    float* tT;  cudaGetSymbolAddress((void**)&tT, g_tT);

    const size_t smem = (size_t)BUFSZ * sizeof(float2);  // 69632 B -> 2 blocks/SM
    cudaFuncSetAttribute(ker_xT_tfft, cudaFuncAttributeMaxDynamicSharedMemorySize, (int)smem);
    cudaFuncSetAttribute(ker_conv, cudaFuncAttributeMaxDynamicSharedMemorySize, (int)smem);

    {
        dim3 blk(256);
        dim3 gt(D_CH / 64, (2 * SEQ) / 64, 1);
        ker_T4<<<gt, blk>>>(t, tT, 2 * SEQ, D_CH, 1);   // also fills g_tw
    }

    ker_xT_tfft<<<256 + 1024, NT, smem>>>(x);           // tfft + x pair-transpose (all batches)
    ker_conv<<<2 * D_CH, NT, smem>>>();
    ker_oP<<<1024, NT>>>(o);
}

// round 14
// speedup vs baseline: 1.0208x; 1.0080x over previous
#include <cuda_runtime.h>
#include <cstdint>

#define N_FFT 8192
#define NT    512
#define D_CH  512
#define SEQ   4096
#define NBATCH 4

// Padded smem index: +1 float2 every 16
#define PADI(i) ((i) + ((i) >> 4))
#define BUFSZ (N_FFT + (N_FFT >> 4))   // 8704 float2 = 69632 B

__device__ float2 g_tw[N_FFT];                       // exp(-2*pi*i*k/N)
__device__ float4 g_tfft[(size_t)D_CH * SEQ];        // [d][q] = (T[q], T[q+4096])
__device__ float2 g_xP[(size_t)2 * D_CH * SEQ];      // [pair][d][n] = (x_b0, x_b1)
__device__ float  g_tT[(size_t)D_CH * 2 * SEQ];
__device__ float2 g_oP[(size_t)2 * D_CH * SEQ];      // [pair][d][n] = (o_b0, o_b1)
__device__ int    g_cnt[16];                         // conv-completion counters per (pair, d/64)

__device__ __forceinline__ float2 cadd(float2 a, float2 b) { return make_float2(a.x + b.x, a.y + b.y); }
__device__ __forceinline__ float2 csub(float2 a, float2 b) { return make_float2(a.x - b.x, a.y - b.y); }
__device__ __forceinline__ float2 cmul(float2 a, float2 b) {
    return make_float2(a.x * b.x - a.y * b.y, a.x * b.y + a.y * b.x);
}
template <bool INV>
__device__ __forceinline__ float2 mulJ(float2 z) {
    return INV ? make_float2(-z.y, z.x) : make_float2(z.y, -z.x);
}
template <bool INV>
__device__ __forceinline__ float2 twc(float2 z, float re, float im) {
    float2 w = make_float2(re, INV ? -im : im);
    return cmul(z, w);
}

template <bool INV>
__device__ __forceinline__ void dft4(float2& a0, float2& a1, float2& a2, float2& a3) {
    float2 t0 = cadd(a0, a2), t1 = csub(a0, a2);
    float2 t2 = cadd(a1, a3), t3 = mulJ<INV>(csub(a1, a3));
    a0 = cadd(t0, t2);
    a1 = cadd(t1, t3);
    a2 = csub(t0, t2);
    a3 = csub(t1, t3);
}

template <bool INV>
__device__ __forceinline__ void dft16(float2 a[16]) {
    const float C1 = 0.92387953251128675613f;
    const float S1 = 0.38268343236508977173f;
    const float H  = 0.70710678118654752440f;
#pragma unroll
    for (int ji = 0; ji < 4; ji++) dft4<INV>(a[ji], a[ji + 4], a[ji + 8], a[ji + 12]);
    a[5]  = twc<INV>(a[5],  C1, -S1);
    a[9]  = twc<INV>(a[9],   H,  -H);
    a[13] = twc<INV>(a[13], S1, -C1);
    a[6]  = twc<INV>(a[6],   H,  -H);
    a[10] = mulJ<INV>(a[10]);
    a[14] = twc<INV>(a[14], -H,  -H);
    a[7]  = twc<INV>(a[7],  S1, -C1);
    a[11] = twc<INV>(a[11], -H,  -H);
    a[15] = twc<INV>(a[15], -C1, S1);
#pragma unroll
    for (int ro = 0; ro < 4; ro++) dft4<INV>(a[4 * ro], a[4 * ro + 1], a[4 * ro + 2], a[4 * ro + 3]);
}

template <bool INV>
__device__ __forceinline__ void tw_load(int sLog, int tid, float2& w1, float2& w8) {
    const int tb = (tid >> sLog) << sLog;
    w1 = g_tw[tb];
    w8 = g_tw[tb << 3];
    if (INV) { w1.y = -w1.y; w8.y = -w8.y; }
}

__device__ __forceinline__ void pass16_write(float2* __restrict__ X, const float2 a[16],
                                             int sLog, int tid, float2 w1, float2 w8) {
    constexpr int SW16[16] = {0,4,8,12, 1,5,9,13, 2,6,10,14, 3,7,11,15};
    const int q = tid & ((1 << sLog) - 1);
    const int p = tid >> sLog;
    const int ob = q + (p << (sLog + 4));
    X[PADI(ob)] = a[SW16[0]];
    float2 w = w1;
#pragma unroll
    for (int r = 1; r < 8; r++) {
        X[PADI(ob + (r << sLog))] = cmul(a[SW16[r]], w);
        w = cmul(w, w1);
    }
    X[PADI(ob + (8 << sLog))] = cmul(a[SW16[8]], w8);
    w = cmul(w8, w1);
#pragma unroll
    for (int r = 9; r < 16; r++) {
        X[PADI(ob + (r << sLog))] = cmul(a[SW16[r]], w);
        w = cmul(w, w1);
    }
}

template <bool INV>
__device__ __forceinline__ void pass16(float2* __restrict__ X, int sLog, int tid) {
    float2 a[16];
#pragma unroll
    for (int r = 0; r < 16; r++) a[r] = X[PADI(tid + 512 * r)];
    dft16<INV>(a);
    float2 w1, w8;
    tw_load<INV>(sLog, tid, w1, w8);   // overlaps the barrier wait
    __syncthreads();
    pass16_write(X, a, sLog, tid, w1, w8);
    __syncthreads();
}

// ---------------------------------------------------------------------------
// x pair-transpose tile (512 threads)
__device__ __forceinline__ void xP_tile(const float* __restrict__ xb0, const float* __restrict__ xb1,
                                        float2* __restrict__ outP, int n0, int d0,
                                        float* t0, float* t1, int tid) {
#pragma unroll
    for (int k = 0; k < 2; k++) {
        int idx = k * 512 + tid;                 // 0..1023
        int n = idx >> 4, c4 = idx & 15;
        float4 v0 = *reinterpret_cast<const float4*>(xb0 + (size_t)(n0 + n) * D_CH + d0 + 4 * c4);
        float4 v1 = *reinterpret_cast<const float4*>(xb1 + (size_t)(n0 + n) * D_CH + d0 + 4 * c4);
        t0[n * 65 + 4 * c4 + 0] = v0.x; t0[n * 65 + 4 * c4 + 1] = v0.y;
        t0[n * 65 + 4 * c4 + 2] = v0.z; t0[n * 65 + 4 * c4 + 3] = v0.w;
        t1[n * 65 + 4 * c4 + 0] = v1.x; t1[n * 65 + 4 * c4 + 1] = v1.y;
        t1[n * 65 + 4 * c4 + 2] = v1.z; t1[n * 65 + 4 * c4 + 3] = v1.w;
    }
    __syncthreads();
#pragma unroll
    for (int k = 0; k < 4; k++) {
        int idx = k * 512 + tid;                 // 0..2047
        int c = idx >> 5, g = idx & 31;
        float4 w = make_float4(t0[(2 * g) * 65 + c], t1[(2 * g) * 65 + c],
                               t0[(2 * g + 1) * 65 + c], t1[(2 * g + 1) * 65 + c]);
        *reinterpret_cast<float4*>(outP + (size_t)(d0 + c) * SEQ + n0 + 2 * g) = w;
    }
}

// o pair-detranspose tile (512 threads). __ldcg: bypass L1 (data produced by other blocks).
__device__ __forceinline__ void oP_tile(const float2* __restrict__ inP,
                                        float* __restrict__ ob0, float* __restrict__ ob1,
                                        int n0, int d0, float* t0, float* t1, int tid) {
#pragma unroll
    for (int k = 0; k < 4; k++) {
        int idx = k * 512 + tid;
        int c = idx >> 5, g = idx & 31;
        float4 v = __ldcg(reinterpret_cast<const float4*>(inP + (size_t)(d0 + c) * SEQ + n0 + 2 * g));
        t0[c * 65 + 2 * g]     = v.x;  t1[c * 65 + 2 * g]     = v.y;
        t0[c * 65 + 2 * g + 1] = v.z;  t1[c * 65 + 2 * g + 1] = v.w;
    }
    __syncthreads();
#pragma unroll
    for (int k = 0; k < 2; k++) {
        int idx = k * 512 + tid;
        int n = idx >> 4, d4 = idx & 15;
        float4 w0 = make_float4(t0[(4 * d4 + 0) * 65 + n], t0[(4 * d4 + 1) * 65 + n],
                                t0[(4 * d4 + 2) * 65 + n], t0[(4 * d4 + 3) * 65 + n]);
        float4 w1 = make_float4(t1[(4 * d4 + 0) * 65 + n], t1[(4 * d4 + 1) * 65 + n],
                                t1[(4 * d4 + 2) * 65 + n], t1[(4 * d4 + 3) * 65 + n]);
        *reinterpret_cast<float4*>(ob0 + (size_t)(n0 + n) * D_CH + d0 + 4 * d4) = w0;
        *reinterpret_cast<float4*>(ob1 + (size_t)(n0 + n) * D_CH + d0 + 4 * d4) = w1;
    }
}

// Conv body for one (pr, d) unit. X = smem buffer.
__device__ __forceinline__ void conv_body(float2* __restrict__ X, int pr, int d, int tid) {
    const float2* xp = g_xP + ((size_t)pr * D_CH + d) * SEQ;

    {
        float2 a[16];
#pragma unroll
        for (int r = 0; r < 8; r++) a[r] = xp[tid + 512 * r];
#pragma unroll
        for (int r = 8; r < 16; r++) a[r] = make_float2(0.0f, 0.0f);
        dft16<false>(a);
        float2 w1, w8;
        tw_load<false>(0, tid, w1, w8);
        pass16_write(X, a, 0, tid, w1, w8);
        __syncthreads();
    }
    pass16<false>(X, 4, tid);
    pass16<false>(X, 8, tid);

    {
        const float4* tf = g_tfft + (size_t)d * SEQ;
        const float inv = 1.0f / (float)N_FFT;
        float2 a[16];
#pragma unroll
        for (int i = 0; i < 8; i++) {
            int q = tid + 512 * i;
            float4 w = tf[q];
            float2 u = X[PADI(q)];
            float2 v = X[PADI(q + 4096)];
            float2 s = cmul(cadd(u, v), make_float2(w.x, w.y));
            float2 dd = cmul(csub(u, v), make_float2(w.z, w.w));
            a[i]     = make_float2(s.x * inv, s.y * inv);
            a[i + 8] = make_float2(dd.x * inv, dd.y * inv);
        }
        dft16<true>(a);
        float2 w1, w8;
        tw_load<true>(0, tid, w1, w8);
        __syncthreads();
        pass16_write(X, a, 0, tid, w1, w8);
        __syncthreads();
    }
    pass16<true>(X, 4, tid);
    pass16<true>(X, 8, tid);

    float2* op = g_oP + ((size_t)pr * D_CH + d) * SEQ;
#pragma unroll
    for (int i = 0; i < 8; i++) {
        int q = tid + 512 * i;
        op[q] = cadd(X[PADI(q)], X[PADI(q + 4096)]);
    }
}

// ---------------------------------------------------------------------------
// float4 tiled transpose (256 threads) for t; first 32 blocks fill g_tw, block 32 zeroes g_cnt.
__global__ void __launch_bounds__(256) ker_T4(const float* __restrict__ in, float* __restrict__ out,
                                              int R, int C, int fill_tw) {
    __shared__ float tile[64][65];
    if (fill_tw && blockIdx.z == 0) {
        int fb = blockIdx.x + blockIdx.y * gridDim.x;
        if (fb < 32) {
            int k = fb * 256 + threadIdx.x;
            float s, c;
            sincospif(-2.0f * (float)k / (float)N_FFT, &s, &c);
            g_tw[k] = make_float2(c, s);
        }
        if (fb == 32 && threadIdx.x < 16) g_cnt[threadIdx.x] = 0;
    }
    const size_t boff = (size_t)blockIdx.z * R * C;
    const float* I = in + boff;
    float* O = out + boff;
    const int c0 = blockIdx.x * 64, r0 = blockIdx.y * 64;
    const int tid = threadIdx.x;
#pragma unroll
    for (int k = 0; k < 4; k++) {
        int idx = k * 256 + tid;
        int row = idx >> 4;
        int c4  = idx & 15;
        float4 v = *reinterpret_cast<const float4*>(I + (size_t)(r0 + row) * C + c0 + 4 * c4);
        tile[row][4 * c4 + 0] = v.x;
        tile[row][4 * c4 + 1] = v.y;
        tile[row][4 * c4 + 2] = v.z;
        tile[row][4 * c4 + 3] = v.w;
    }
    __syncthreads();
#pragma unroll
    for (int k = 0; k < 4; k++) {
        int idx = k * 256 + tid;
        int c  = idx >> 4;
        int r4 = idx & 15;
        float4 v = make_float4(tile[4 * r4 + 0][c], tile[4 * r4 + 1][c],
                               tile[4 * r4 + 2][c], tile[4 * r4 + 3][c]);
        *reinterpret_cast<float4*>(O + (size_t)(c0 + c) * R + r0 + 4 * r4) = v;
    }
}

// Fat kernel: blocks [0,256) tfft; blocks [256,1280) x pair-transpose.
__global__ void __launch_bounds__(NT, 2) ker_xT_tfft(const float* __restrict__ x) {
    extern __shared__ float2 sm[];
    const int tid = threadIdx.x;

    if (blockIdx.x >= 256) {
        const int tt = blockIdx.x - 256;              // 0..1023
        const int p = tt >> 9;                        // pair 0,1
        const int rem = tt & 511;
        const int d0 = (rem & 7) * 64;
        const int n0 = (rem >> 3) * 64;
        const float* xb0 = x + (size_t)(2 * p) * SEQ * D_CH;
        const float* xb1 = xb0 + (size_t)SEQ * D_CH;
        float* t0 = reinterpret_cast<float*>(sm);
        float* t1 = t0 + 64 * 65;
        xP_tile(xb0, xb1, g_xP + (size_t)p * D_CH * SEQ, n0, d0, t0, t1, tid);
        return;
    }

    // tfft: block handles channels (2c0, 2c0+1) as real+imag of one FFT
    float2* X = sm;
    const int c0 = blockIdx.x;
    const float* t0 = g_tT + (size_t)(2 * c0) * N_FFT;
    const float* t1 = t0 + N_FFT;
    {
        float2 a[16];
#pragma unroll
        for (int r = 0; r < 16; r++)
            a[r] = make_float2(t0[tid + 512 * r], t1[tid + 512 * r]);
        dft16<false>(a);
        float2 w1, w8;
        tw_load<false>(0, tid, w1, w8);
        pass16_write(X, a, 0, tid, w1, w8);
        __syncthreads();
    }
    pass16<false>(X, 4, tid);
    pass16<false>(X, 8, tid);

    // Fused: final radix-2 + Hermitian unpack, written in (T[q], T[q+4096]) pair layout.
    float4* out0 = g_tfft + (size_t)(2 * c0) * SEQ;
    float4* out1 = out0 + SEQ;
#pragma unroll
    for (int i = 0; i < 8; i++) {
        int k = tid + 512 * i;
        float2 ua = X[PADI(k)], ub = X[PADI(k + 4096)];
        float2 Zk  = cadd(ua, ub);
        float2 Zk2 = csub(ua, ub);
        int m = (4096 - k) & 4095;
        float2 va = X[PADI(m)], vb = X[PADI(m + 4096)];
        bool kz = (k == 0);
        float2 Zn  = kz ? cadd(va, vb) : csub(va, vb);
        float2 Zn2 = kz ? csub(va, vb) : cadd(va, vb);
        out0[k] = make_float4(0.5f * (Zk.x + Zn.x),  0.5f * (Zk.y - Zn.y),
                              0.5f * (Zk2.x + Zn2.x), 0.5f * (Zk2.y - Zn2.y));
        out1[k] = make_float4(0.5f * (Zk.y + Zn.y),  -0.5f * (Zk.x - Zn.x),
                              0.5f * (Zk2.y + Zn2.y), -0.5f * (Zk2.x - Zn2.x));
    }
}

// Fat kernel: blocks [0,1024) conv (producers, signal per (pair, d/64) group);
// blocks [1024,2048) o-detranspose tiles (consumers, spin on their group's counter).
// Deadlock-free: producers never wait; consumers have higher block ids so producers
// are scheduled first.
__global__ void __launch_bounds__(NT, 2) ker_conv_oP(float* __restrict__ o) {
    extern __shared__ float2 sm[];
    const int tid = threadIdx.x;

    if (blockIdx.x < 1024) {
        const int pr = blockIdx.x >> 9;
        const int d = blockIdx.x & (D_CH - 1);
        conv_body(sm, pr, d, tid);
        __threadfence();
        __syncthreads();
        if (tid == 0) atomicAdd(&g_cnt[pr * 8 + (d >> 6)], 1);
        return;
    }

    const int tt = blockIdx.x - 1024;                 // 0..1023
    const int p = tt >> 9;
    const int rem = tt & 511;
    const int dg = rem & 7;
    const int d0 = dg * 64;
    const int n0 = (rem >> 3) * 64;
    if (tid == 0) {
        volatile int* c = g_cnt;
        while (c[p * 8 + dg] < 64) __nanosleep(200);
    }
    __syncthreads();
    __threadfence();
    float* t0 = reinterpret_cast<float*>(sm);
    float* t1 = t0 + 64 * 65;
    float* ob0 = o + (size_t)(2 * p) * SEQ * D_CH;
    float* ob1 = ob0 + (size_t)SEQ * D_CH;
    oP_tile(g_oP + (size_t)p * D_CH * SEQ, ob0, ob1, n0, d0, t0, t1, tid);
}

extern "C" void kernel_launch(void* const* d_in, const int* in_sizes, int n_in,
                              void* d_out, int out_size) {
    const float* x = (const float*)d_in[0];
    const float* t = (const float*)d_in[1];
    if (n_in >= 2 && in_sizes[0] < in_sizes[1]) {
        const float* tmp = x; x = t; t = tmp;
    }
    float* o = (float*)d_out;

    float* tT;  cudaGetSymbolAddress((void**)&tT, g_tT);

    const size_t smem = (size_t)BUFSZ * sizeof(float2);  // 69632 B -> 2 blocks/SM
    cudaFuncSetAttribute(ker_xT_tfft, cudaFuncAttributeMaxDynamicSharedMemorySize, (int)smem);
    cudaFuncSetAttribute(ker_conv_oP, cudaFuncAttributeMaxDynamicSharedMemorySize, (int)smem);

    {
        dim3 blk(256);
        dim3 gt(D_CH / 64, (2 * SEQ) / 64, 1);
        ker_T4<<<gt, blk>>>(t, tT, 2 * SEQ, D_CH, 1);   // fills g_tw, zeroes g_cnt
    }

    ker_xT_tfft<<<256 + 1024, NT, smem>>>(x);           // tfft + x pair-transpose
    ker_conv_oP<<<2048, NT, smem>>>(o);                 // conv + overlapped o-detranspose
}